// round 1
// baseline (speedup 1.0000x reference)
#include <cuda_runtime.h>
#include <math.h>

// Problem constants
#define BQ 16
#define HD 512
#define LL 2048
#define NL 4
#define NN 32

// ---------------- scratch (static __device__, no allocs) ----------------
__device__ float g_H[(size_t)BQ * HD * LL];        // h buffer (B,H,L)
__device__ float g_Y[(size_t)BQ * HD * LL];        // gelu(ssm) buffer
__device__ float g_Z[(size_t)BQ * 2 * HD * LL];    // GLU pre-activation (B,2H,L)
__device__ float g_wre[NL * HD * NN];
__device__ float g_wim[NL * HD * NN];
__device__ float g_cre[NL * HD * NN];
__device__ float g_cim[NL * HD * NN];

// ---------------- kernel-parameter precompute ----------------
// w = exp(dt*A), Cc = (C_re + i C_im) * expm1(dt*A) / A
__global__ __launch_bounds__(256)
void precompute_kernel(const float* __restrict__ log_dt,
                       const float* __restrict__ log_A_real,
                       const float* __restrict__ A_imag,
                       const float* __restrict__ C_re,
                       const float* __restrict__ C_im)
{
    int idx = blockIdx.x * 256 + threadIdx.x;            // [layer][h][n]
    if (idx >= NL * HD * NN) return;
    int h = (idx >> 5) & (HD - 1);
    int l = idx >> 14;

    float dt = expf(log_dt[l * HD + h]);
    float a = -expf(log_A_real[idx]);
    float b = A_imag[idx];
    float xr = dt * a, xi = dt * b;
    float er = expf(xr);
    float c = cosf(xi), s = sinf(xi);
    g_wre[idx] = er * c;
    g_wim[idx] = er * s;
    // expm1(xr + i*xi) = expm1(xr)*cos(xi) - 2*sin^2(xi/2)  +  i * e^xr * sin(xi)
    float sh = sinf(0.5f * xi);
    float Ere = expm1f(xr) * c - 2.f * sh * sh;
    float Eim = er * s;
    float den = a * a + b * b;
    float Fre = (Ere * a + Eim * b) / den;
    float Fim = (Eim * a - Ere * b) / den;
    float cr = C_re[idx], ci = C_im[idx];
    g_cre[idx] = cr * Fre - ci * Fim;
    g_cim[idx] = cr * Fim + ci * Fre;
}

// ---------------- fp32 GEMM: C[b] = act(W @ X[b] (+bias)) ----------------
// A: (M,K) row-major weights (shared over batch)
// B: (batch, K, N) row-major, C: (batch, M, N)
// EPI: 0 = relu, 1 = +bias (no act)
__device__ __forceinline__ float4 quant4(float4 v)
{
    v.x = rintf(v.x * 64.f) * 0.015625f;
    v.y = rintf(v.y * 64.f) * 0.015625f;
    v.z = rintf(v.z * 64.f) * 0.015625f;
    v.w = rintf(v.w * 64.f) * 0.015625f;
    return v;
}

template <int EPI, bool QUANT>
__global__ __launch_bounds__(256, 2)
void gemm_kernel(const float* __restrict__ A, const float* __restrict__ B,
                 float* __restrict__ C, const float* __restrict__ bias,
                 int M, int N, int K)
{
    __shared__ float As[2][8][128];
    __shared__ float Bs[2][8][128];
    const int tid = threadIdx.x;
    const size_t bz = blockIdx.z;
    const float* Bb = B + bz * (size_t)K * N;
    float* Cb = C + bz * (size_t)M * N;
    const int m0 = blockIdx.y * 128;
    const int n0 = blockIdx.x * 128;

    const int arow = tid >> 1;
    const int acol = (tid & 1) << 2;
    const int brow = tid >> 5;
    const int bcol = (tid & 31) << 2;
    const int tx = tid & 15, ty = tid >> 4;
    const int tm = ty << 2, tn = tx << 2;

    float acc[8][8];
#pragma unroll
    for (int i = 0; i < 8; ++i)
#pragma unroll
        for (int j = 0; j < 8; ++j) acc[i][j] = 0.f;

    float4 av = *reinterpret_cast<const float4*>(&A[(size_t)(m0 + arow) * K + acol]);
    float4 bv = *reinterpret_cast<const float4*>(&Bb[(size_t)brow * N + n0 + bcol]);
    if (QUANT) bv = quant4(bv);
    As[0][acol + 0][arow] = av.x;
    As[0][acol + 1][arow] = av.y;
    As[0][acol + 2][arow] = av.z;
    As[0][acol + 3][arow] = av.w;
    *reinterpret_cast<float4*>(&Bs[0][brow][bcol]) = bv;
    __syncthreads();

    const int nk = K >> 3;
    for (int kt = 0; kt < nk; ++kt) {
        const int buf = kt & 1;
        float4 av2, bv2;
        if (kt + 1 < nk) {
            av2 = *reinterpret_cast<const float4*>(
                &A[(size_t)(m0 + arow) * K + (kt + 1) * 8 + acol]);
            bv2 = *reinterpret_cast<const float4*>(
                &Bb[(size_t)((kt + 1) * 8 + brow) * N + n0 + bcol]);
        }
#pragma unroll
        for (int kk = 0; kk < 8; ++kk) {
            float a[8], b[8];
            *reinterpret_cast<float4*>(&a[0]) =
                *reinterpret_cast<const float4*>(&As[buf][kk][tm]);
            *reinterpret_cast<float4*>(&a[4]) =
                *reinterpret_cast<const float4*>(&As[buf][kk][tm + 64]);
            *reinterpret_cast<float4*>(&b[0]) =
                *reinterpret_cast<const float4*>(&Bs[buf][kk][tn]);
            *reinterpret_cast<float4*>(&b[4]) =
                *reinterpret_cast<const float4*>(&Bs[buf][kk][tn + 64]);
#pragma unroll
            for (int i = 0; i < 8; ++i)
#pragma unroll
                for (int j = 0; j < 8; ++j)
                    acc[i][j] = fmaf(a[i], b[j], acc[i][j]);
        }
        if (kt + 1 < nk) {
            const int nb = buf ^ 1;
            As[nb][acol + 0][arow] = av2.x;
            As[nb][acol + 1][arow] = av2.y;
            As[nb][acol + 2][arow] = av2.z;
            As[nb][acol + 3][arow] = av2.w;
            if (QUANT) bv2 = quant4(bv2);
            *reinterpret_cast<float4*>(&Bs[nb][brow][bcol]) = bv2;
        }
        __syncthreads();
    }

#pragma unroll
    for (int i = 0; i < 8; ++i) {
        const int m = m0 + ((i < 4) ? (tm + i) : (tm + 64 + i - 4));
        float bb = (EPI == 1) ? bias[m] : 0.f;
        float o[8];
#pragma unroll
        for (int j = 0; j < 8; ++j) {
            float v = acc[i][j] + bb;
            if (EPI == 0) v = fmaxf(v, 0.f);
            o[j] = v;
        }
        *reinterpret_cast<float4*>(&Cb[(size_t)m * N + n0 + tn]) =
            *reinterpret_cast<float4*>(&o[0]);
        *reinterpret_cast<float4*>(&Cb[(size_t)m * N + n0 + tn + 64]) =
            *reinterpret_cast<float4*>(&o[4]);
    }
}

// ---------------- SSM scan: y = gelu(2*Re sum_n Cc*s + D*h) ----------------
// 8 lanes per (b,h) channel, 4 complex states per lane (N2=32).
__global__ __launch_bounds__(256)
void ssm_scan_kernel(const float* __restrict__ hbuf, float* __restrict__ ybuf,
                     const float* __restrict__ wre, const float* __restrict__ wim,
                     const float* __restrict__ ccre, const float* __restrict__ ccim,
                     const float* __restrict__ Dv)
{
    int gt = blockIdx.x * 256 + threadIdx.x;
    int q = gt & 7;
    int grp = gt >> 3;               // b*HD + h, 0..8191
    int hh = grp & (HD - 1);
    const float* hrow = hbuf + (size_t)grp * LL;
    float* yrow = ybuf + (size_t)grp * LL;

    int pbase = hh * NN + q * 4;
    float4 w_r = *reinterpret_cast<const float4*>(&wre[pbase]);
    float4 w_i = *reinterpret_cast<const float4*>(&wim[pbase]);
    float4 c_r = *reinterpret_cast<const float4*>(&ccre[pbase]);
    float4 c_i = *reinterpret_cast<const float4*>(&ccim[pbase]);
    float wr[4] = {w_r.x, w_r.y, w_r.z, w_r.w};
    float wi[4] = {w_i.x, w_i.y, w_i.z, w_i.w};
    float cr[4] = {c_r.x, c_r.y, c_r.z, c_r.w};
    float ci[4] = {c_i.x, c_i.y, c_i.z, c_i.w};
    float Dh = Dv[hh];

    float sr[4] = {0.f, 0.f, 0.f, 0.f};
    float si[4] = {0.f, 0.f, 0.f, 0.f};

    for (int t0 = 0; t0 < LL; t0 += 8) {
        float umine = 0.f, ykeep = 0.f;
#pragma unroll
        for (int j = 0; j < 8; ++j) {
            float u = hrow[t0 + j];
#pragma unroll
            for (int k = 0; k < 4; ++k) {
                float nr = fmaf(wr[k], sr[k], u);
                nr = fmaf(-wi[k], si[k], nr);
                float ni = wr[k] * si[k];
                ni = fmaf(wi[k], sr[k], ni);
                sr[k] = nr;
                si[k] = ni;
            }
            float acc = 0.f;
#pragma unroll
            for (int k = 0; k < 4; ++k) {
                acc = fmaf(cr[k], sr[k], acc);
                acc = fmaf(-ci[k], si[k], acc);
            }
            acc += __shfl_xor_sync(0xffffffffu, acc, 1);
            acc += __shfl_xor_sync(0xffffffffu, acc, 2);
            acc += __shfl_xor_sync(0xffffffffu, acc, 4);
            if (j == q) { umine = u; ykeep = acc; }
        }
        float yv = fmaf(Dh, umine, 2.f * ykeep);
        float gv = 0.5f * yv * (1.f + erff(yv * 0.70710678118654752f));
        yrow[t0 + q] = gv;
    }
}

// ---------------- GLU + residual + channel LayerNorm ----------------
// Z: (B, 2H, L). H := LN( Z[:, :H]*sigmoid(Z[:, H:]) + H )
__global__ __launch_bounds__(256)
void glu_res_ln_kernel(const float* __restrict__ Z, float* __restrict__ Hb_,
                       const float* __restrict__ gamma, const float* __restrict__ beta)
{
    __shared__ float ssum[4][64];
    __shared__ float ssq[4][64];
    const int b = blockIdx.y;
    const int tl = threadIdx.x & 63;
    const int slab = threadIdx.x >> 6;
    const size_t t = (size_t)blockIdx.x * 64 + tl;
    const float* Zb = Z + (size_t)b * (2 * HD) * LL;
    float* Hbp = Hb_ + (size_t)b * HD * LL;

    float s = 0.f, s2 = 0.f;
    for (int c = slab * 128; c < slab * 128 + 128; ++c) {
        float z1 = Zb[(size_t)c * LL + t];
        float z2 = Zb[(size_t)(c + HD) * LL + t];
        float hp = Hbp[(size_t)c * LL + t];
        float sg = 1.f / (1.f + expf(-z2));
        float v = fmaf(z1, sg, hp);
        Hbp[(size_t)c * LL + t] = v;
        s += v;
        s2 = fmaf(v, v, s2);
    }
    ssum[slab][tl] = s;
    ssq[slab][tl] = s2;
    __syncthreads();
    float st = ssum[0][tl] + ssum[1][tl] + ssum[2][tl] + ssum[3][tl];
    float st2 = ssq[0][tl] + ssq[1][tl] + ssq[2][tl] + ssq[3][tl];
    float mu = st * (1.f / HD);
    float var = st2 * (1.f / HD) - mu * mu;
    float rstd = rsqrtf(var + 1e-5f);
    for (int c = slab * 128; c < slab * 128 + 128; ++c) {
        float v = Hbp[(size_t)c * LL + t];
        Hbp[(size_t)c * LL + t] = (v - mu) * rstd * gamma[c] + beta[c];
    }
}

// ---------------- launch ----------------
extern "C" void kernel_launch(void* const* d_in, const int* in_sizes, int n_in,
                              void* d_out, int out_size)
{
    const float* x = (const float*)d_in[0];
    const float* W_enc = (const float*)d_in[1];
    const float* W_dec = (const float*)d_in[2];
    const float* log_dt = (const float*)d_in[3];
    const float* log_A_real = (const float*)d_in[4];
    const float* A_imag = (const float*)d_in[5];
    const float* C_re = (const float*)d_in[6];
    const float* C_im = (const float*)d_in[7];
    const float* Dv = (const float*)d_in[8];
    const float* W_out = (const float*)d_in[9];
    const float* b_out = (const float*)d_in[10];
    const float* ln_g = (const float*)d_in[11];
    const float* ln_b = (const float*)d_in[12];
    float* out = (float*)d_out;

    float *pH, *pY, *pZ, *pwre, *pwim, *pcre, *pcim;
    cudaGetSymbolAddress((void**)&pH, g_H);
    cudaGetSymbolAddress((void**)&pY, g_Y);
    cudaGetSymbolAddress((void**)&pZ, g_Z);
    cudaGetSymbolAddress((void**)&pwre, g_wre);
    cudaGetSymbolAddress((void**)&pwim, g_wim);
    cudaGetSymbolAddress((void**)&pcre, g_cre);
    cudaGetSymbolAddress((void**)&pcim, g_cim);

    precompute_kernel<<<(NL * HD * NN + 255) / 256, 256>>>(log_dt, log_A_real,
                                                           A_imag, C_re, C_im);

    // encoder: h = relu(W_enc @ quant(x))
    gemm_kernel<0, true><<<dim3(LL / 128, HD / 128, BQ), 256>>>(
        W_enc, x, pH, nullptr, HD, LL, HD);

    for (int l = 0; l < NL; ++l) {
        int po = l * HD * NN;
        ssm_scan_kernel<<<(BQ * HD * 8) / 256, 256>>>(
            pH, pY, pwre + po, pwim + po, pcre + po, pcim + po, Dv + l * HD);
        gemm_kernel<1, false><<<dim3(LL / 128, (2 * HD) / 128, BQ), 256>>>(
            W_out + (size_t)l * 2 * HD * HD, pY, pZ, b_out + l * 2 * HD,
            2 * HD, LL, HD);
        glu_res_ln_kernel<<<dim3(LL / 64, BQ), 256>>>(pZ, pH, ln_g + l * HD,
                                                      ln_b + l * HD);
    }

    // decoder: out = relu(W_dec @ h)
    gemm_kernel<0, false><<<dim3(LL / 128, HD / 128, BQ), 256>>>(
        W_dec, pH, out, nullptr, HD, LL, HD);
}

// round 3
// speedup vs baseline: 1.5412x; 1.5412x over previous
#include <cuda_runtime.h>
#include <cuda_bf16.h>
#include <stdint.h>
#include <math.h>

#define BQ 16
#define HD 512
#define LL 2048
#define NL 4
#define NN 32
#define NTOT (BQ * LL)  // 32768 total columns

// ---------------- scratch (static __device__, no allocs) ----------------
__device__ float g_H[(size_t)BQ * HD * LL];
__device__ float g_Y[(size_t)BQ * HD * LL];
__device__ float g_Z[(size_t)BQ * 2 * HD * LL];
__device__ __nv_bfloat16 g_Bth[(size_t)NTOT * HD];   // activations (n,k) hi
__device__ __nv_bfloat16 g_Btl[(size_t)NTOT * HD];   // activations (n,k) lo
#define W_ENC_OFF 0
#define W_OUT_OFF (HD * HD)
#define W_DEC_OFF (HD * HD + NL * 2 * HD * HD)
#define W_ELEMS (2 * HD * HD + NL * 2 * HD * HD)
__device__ __nv_bfloat16 g_Wh[W_ELEMS];
__device__ __nv_bfloat16 g_Wl[W_ELEMS];
__device__ float g_wre[NL * HD * NN];
__device__ float g_wim[NL * HD * NN];
__device__ float g_cre[NL * HD * NN];
__device__ float g_cim[NL * HD * NN];

// ---------------- helpers ----------------
__device__ __forceinline__ uint32_t smem_u32(const void* p)
{
    uint32_t a;
    asm("{ .reg .u64 t; cvta.to.shared.u64 t, %1; cvt.u32.u64 %0, t; }"
        : "=r"(a) : "l"(p));
    return a;
}

__device__ __forceinline__ void cp_async16(uint32_t dst, const void* src)
{
    asm volatile("cp.async.cg.shared.global [%0], [%1], 16;" :: "r"(dst), "l"(src));
}
#define CP_COMMIT() asm volatile("cp.async.commit_group;" ::: "memory")
#define CP_WAIT(n)  asm volatile("cp.async.wait_group %0;" :: "n"(n) : "memory")

__device__ __forceinline__ void ldmx4(uint32_t* r, uint32_t addr)
{
    asm volatile("ldmatrix.sync.aligned.m8n8.x4.shared.b16 {%0,%1,%2,%3}, [%4];"
                 : "=r"(r[0]), "=r"(r[1]), "=r"(r[2]), "=r"(r[3]) : "r"(addr));
}

__device__ __forceinline__ void mma16816(float* c, const uint32_t* a,
                                         const uint32_t* b)
{
    asm volatile(
        "mma.sync.aligned.m16n8k16.row.col.f32.bf16.bf16.f32 "
        "{%0,%1,%2,%3}, {%4,%5,%6,%7}, {%8,%9}, {%0,%1,%2,%3};"
        : "+f"(c[0]), "+f"(c[1]), "+f"(c[2]), "+f"(c[3])
        : "r"(a[0]), "r"(a[1]), "r"(a[2]), "r"(a[3]), "r"(b[0]), "r"(b[1]));
}

// ---------------- parameter precompute ----------------
__global__ __launch_bounds__(256)
void precompute_kernel(const float* __restrict__ log_dt,
                       const float* __restrict__ log_A_real,
                       const float* __restrict__ A_imag,
                       const float* __restrict__ C_re,
                       const float* __restrict__ C_im)
{
    int idx = blockIdx.x * 256 + threadIdx.x;
    if (idx >= NL * HD * NN) return;
    int h = (idx >> 5) & (HD - 1);
    int l = idx >> 14;
    float dt = expf(log_dt[l * HD + h]);
    float a = -expf(log_A_real[idx]);
    float b = A_imag[idx];
    float xr = dt * a, xi = dt * b;
    float er = expf(xr);
    float c = cosf(xi), s = sinf(xi);
    g_wre[idx] = er * c;
    g_wim[idx] = er * s;
    float sh = sinf(0.5f * xi);
    float Ere = expm1f(xr) * c - 2.f * sh * sh;
    float Eim = er * s;
    float den = a * a + b * b;
    float Fre = (Ere * a + Eim * b) / den;
    float Fim = (Eim * a - Ere * b) / den;
    float cr = C_re[idx], ci = C_im[idx];
    g_cre[idx] = cr * Fre - ci * Fim;
    g_cim[idx] = cr * Fim + ci * Fre;
}

// ---------------- weight split fp32 -> bf16 hi/lo ----------------
__global__ __launch_bounds__(256)
void split_w_kernel(const float* __restrict__ src, __nv_bfloat16* __restrict__ hi,
                    __nv_bfloat16* __restrict__ lo, int n)
{
    int i = blockIdx.x * 256 + threadIdx.x;
    if (i >= n) return;
    float v = src[i];
    __nv_bfloat16 h = __float2bfloat16(v);
    hi[i] = h;
    lo[i] = __float2bfloat16(v - __bfloat162float(h));
}

// ---------------- activation transpose + split: (B,C,L) -> [(b*L+t)*C + c] ----
template <bool QUANT>
__global__ __launch_bounds__(256)
void transpose_split_kernel(const float* __restrict__ src,
                            __nv_bfloat16* __restrict__ dhi,
                            __nv_bfloat16* __restrict__ dlo)
{
    __shared__ float tile[32][33];
    const int b = blockIdx.z;
    const int c0 = blockIdx.y * 32;
    const int t0 = blockIdx.x * 32;
    const int tx = threadIdx.x & 31, ty = threadIdx.x >> 5;
#pragma unroll
    for (int i = 0; i < 32; i += 8) {
        float v = src[((size_t)b * HD + c0 + ty + i) * LL + t0 + tx];
        if (QUANT) v = rintf(v * 64.f) * 0.015625f;
        tile[ty + i][tx] = v;
    }
    __syncthreads();
#pragma unroll
    for (int i = 0; i < 32; i += 8) {
        int t = t0 + ty + i;
        int c = c0 + tx;
        float v = tile[tx][ty + i];
        __nv_bfloat16 h = __float2bfloat16(v);
        size_t o = ((size_t)b * LL + t) * HD + c;
        dhi[o] = h;
        dlo[o] = __float2bfloat16(v - __bfloat162float(h));
    }
}

// ---------------- HMMA GEMM (3x bf16 split, fp32 acc) ----------------
// D[m][n] = sum_k W[m][k]*X[n][k]; out[b][m][t], n = b*2048 + t
// CTA tile 128(M) x 128(N), K-chunk 64, double buffered cp.async.
// 8 warps as 4(M)x2(N): each warp 32x64.
#define KC 64
#define TILE_SEGS 1024              // 128 rows * 8 segs(16B)
#define TILE_BYTES 16384            // 128 * 64 * 2B
#define STAGE_BYTES (4 * TILE_BYTES)
#define GEMM_SMEM (2 * STAGE_BYTES) // 131072

template <int EPI>
__global__ __launch_bounds__(256, 1)
void gemm_mma(const __nv_bfloat16* __restrict__ Wh, const __nv_bfloat16* __restrict__ Wl,
              const __nv_bfloat16* __restrict__ Xh, const __nv_bfloat16* __restrict__ Xl,
              float* __restrict__ out, const float* __restrict__ bias, int M)
{
    extern __shared__ char smem[];
    const uint32_t sb = smem_u32(smem);
    const int tid = threadIdx.x;
    const int wid = tid >> 5, lane = tid & 31;
    const int wm = wid >> 1, wn = wid & 1;
    const int n0 = blockIdx.x * 128;
    const int m0 = blockIdx.y * 128;
    const int lr = lane & 7, lg = lane >> 3;

    float acc[2][8][4];
#pragma unroll
    for (int i = 0; i < 2; ++i)
#pragma unroll
        for (int j = 0; j < 8; ++j)
#pragma unroll
            for (int q = 0; q < 4; ++q) acc[i][j][q] = 0.f;

    // cp.async one K-chunk (64 cols) of all 4 tiles into stage st
    auto load_chunk = [&](int kc, int st) {
        const uint32_t base = sb + st * STAGE_BYTES;
        const size_t gk = (size_t)kc * KC;
#pragma unroll
        for (int i = 0; i < 4; ++i) {
            int lin = i * 256 + tid;
            int row = lin >> 3, seg = lin & 7;
            uint32_t soff = row * 128 + (((seg ^ (row & 7))) << 4);
            const size_t wgo = (size_t)(m0 + row) * HD + gk + seg * 8;
            const size_t xgo = (size_t)(n0 + row) * HD + gk + seg * 8;
            cp_async16(base + soff, Wh + wgo);
            cp_async16(base + TILE_BYTES + soff, Wl + wgo);
            cp_async16(base + 2 * TILE_BYTES + soff, Xh + xgo);
            cp_async16(base + 3 * TILE_BYTES + soff, Xl + xgo);
        }
        CP_COMMIT();
    };

    load_chunk(0, 0);

    const int NCH = HD / KC;  // 8
    for (int c = 0; c < NCH; ++c) {
        if (c + 1 < NCH) {
            load_chunk(c + 1, (c + 1) & 1);
            CP_WAIT(1);
        } else {
            CP_WAIT(0);
        }
        __syncthreads();

        const uint32_t stg = sb + (c & 1) * STAGE_BYTES;
#pragma unroll
        for (int ks = 0; ks < 4; ++ks) {
            uint32_t a[2][2][4];   // [half][mi][reg]
            uint32_t b[2][4][4];   // [half][n16 group][reg]
            // A fragments: rows m, two m16 tiles
#pragma unroll
            for (int mi = 0; mi < 2; ++mi) {
                int arow = wm * 32 + mi * 16 + lr + (lg & 1) * 8;
                int aseg = ks * 2 + (lg >> 1);
                uint32_t off = arow * 128 + ((aseg ^ (arow & 7)) << 4);
                ldmx4(a[0][mi], stg + off);
                ldmx4(a[1][mi], stg + TILE_BYTES + off);
            }
            // B fragments: rows n, four n16 groups
#pragma unroll
            for (int g = 0; g < 4; ++g) {
                int brow = wn * 64 + g * 16 + lr + (lg >> 1) * 8;
                int bseg = ks * 2 + (lg & 1);
                uint32_t off = brow * 128 + ((bseg ^ (brow & 7)) << 4);
                ldmx4(b[0][g], stg + 2 * TILE_BYTES + off);
                ldmx4(b[1][g], stg + 3 * TILE_BYTES + off);
            }
#pragma unroll
            for (int mi = 0; mi < 2; ++mi)
#pragma unroll
                for (int j = 0; j < 8; ++j) {
                    const int g = j >> 1, p = (j & 1) * 2;
                    uint32_t bh[2] = {b[0][g][p], b[0][g][p + 1]};
                    uint32_t bl[2] = {b[1][g][p], b[1][g][p + 1]};
                    mma16816(acc[mi][j], a[0][mi], bh);  // ah*bh
                    mma16816(acc[mi][j], a[0][mi], bl);  // ah*bl
                    mma16816(acc[mi][j], a[1][mi], bh);  // al*bh
                }
        }
        __syncthreads();
    }

    // epilogue
#pragma unroll
    for (int mi = 0; mi < 2; ++mi) {
        const int mrow0 = m0 + wm * 32 + mi * 16 + (lane >> 2);
        float b0 = (EPI == 1) ? bias[mrow0] : 0.f;
        float b1 = (EPI == 1) ? bias[mrow0 + 8] : 0.f;
#pragma unroll
        for (int j = 0; j < 8; ++j) {
            const int n = n0 + wn * 64 + j * 8 + (lane & 3) * 2;
            const int bb = n >> 11;
            const int t = n & (LL - 1);
            float2 v0, v1;
            v0.x = acc[mi][j][0] + b0;
            v0.y = acc[mi][j][1] + b0;
            v1.x = acc[mi][j][2] + b1;
            v1.y = acc[mi][j][3] + b1;
            if (EPI == 0) {
                v0.x = fmaxf(v0.x, 0.f); v0.y = fmaxf(v0.y, 0.f);
                v1.x = fmaxf(v1.x, 0.f); v1.y = fmaxf(v1.y, 0.f);
            }
            *reinterpret_cast<float2*>(out + ((size_t)bb * M + mrow0) * LL + t) = v0;
            *reinterpret_cast<float2*>(out + ((size_t)bb * M + mrow0 + 8) * LL + t) = v1;
        }
    }
}

// ---------------- SSM scan ----------------
__global__ __launch_bounds__(256)
void ssm_scan_kernel(const float* __restrict__ hbuf, float* __restrict__ ybuf,
                     const float* __restrict__ wre, const float* __restrict__ wim,
                     const float* __restrict__ ccre, const float* __restrict__ ccim,
                     const float* __restrict__ Dv)
{
    int gt = blockIdx.x * 256 + threadIdx.x;
    int q = gt & 7;
    int grp = gt >> 3;
    int hh = grp & (HD - 1);
    const float* hrow = hbuf + (size_t)grp * LL;
    float* yrow = ybuf + (size_t)grp * LL;

    int pbase = hh * NN + q * 4;
    float4 w_r = *reinterpret_cast<const float4*>(&wre[pbase]);
    float4 w_i = *reinterpret_cast<const float4*>(&wim[pbase]);
    float4 c_r = *reinterpret_cast<const float4*>(&ccre[pbase]);
    float4 c_i = *reinterpret_cast<const float4*>(&ccim[pbase]);
    float wr[4] = {w_r.x, w_r.y, w_r.z, w_r.w};
    float wi[4] = {w_i.x, w_i.y, w_i.z, w_i.w};
    float cr[4] = {c_r.x, c_r.y, c_r.z, c_r.w};
    float ci[4] = {c_i.x, c_i.y, c_i.z, c_i.w};
    float Dh = Dv[hh];

    float sr[4] = {0.f, 0.f, 0.f, 0.f};
    float si[4] = {0.f, 0.f, 0.f, 0.f};

    for (int t0 = 0; t0 < LL; t0 += 8) {
        float umine = 0.f, ykeep = 0.f;
#pragma unroll
        for (int j = 0; j < 8; ++j) {
            float u = hrow[t0 + j];
#pragma unroll
            for (int k = 0; k < 4; ++k) {
                float nr = fmaf(wr[k], sr[k], u);
                nr = fmaf(-wi[k], si[k], nr);
                float ni = wr[k] * si[k];
                ni = fmaf(wi[k], sr[k], ni);
                sr[k] = nr;
                si[k] = ni;
            }
            float acc = 0.f;
#pragma unroll
            for (int k = 0; k < 4; ++k) {
                acc = fmaf(cr[k], sr[k], acc);
                acc = fmaf(-ci[k], si[k], acc);
            }
            acc += __shfl_xor_sync(0xffffffffu, acc, 1);
            acc += __shfl_xor_sync(0xffffffffu, acc, 2);
            acc += __shfl_xor_sync(0xffffffffu, acc, 4);
            if (j == q) { umine = u; ykeep = acc; }
        }
        float yv = fmaf(Dh, umine, 2.f * ykeep);
        float gv = 0.5f * yv * (1.f + erff(yv * 0.70710678118654752f));
        yrow[t0 + q] = gv;
    }
}

// ---------------- GLU + residual + channel LayerNorm ----------------
__global__ __launch_bounds__(256)
void glu_res_ln_kernel(const float* __restrict__ Z, float* __restrict__ Hb_,
                       const float* __restrict__ gamma, const float* __restrict__ beta)
{
    __shared__ float ssum[4][64];
    __shared__ float ssq[4][64];
    const int b = blockIdx.y;
    const int tl = threadIdx.x & 63;
    const int slab = threadIdx.x >> 6;
    const size_t t = (size_t)blockIdx.x * 64 + tl;
    const float* Zb = Z + (size_t)b * (2 * HD) * LL;
    float* Hbp = Hb_ + (size_t)b * HD * LL;

    float s = 0.f, s2 = 0.f;
    for (int c = slab * 128; c < slab * 128 + 128; ++c) {
        float z1 = Zb[(size_t)c * LL + t];
        float z2 = Zb[(size_t)(c + HD) * LL + t];
        float hp = Hbp[(size_t)c * LL + t];
        float sg = 1.f / (1.f + expf(-z2));
        float v = fmaf(z1, sg, hp);
        Hbp[(size_t)c * LL + t] = v;
        s += v;
        s2 = fmaf(v, v, s2);
    }
    ssum[slab][tl] = s;
    ssq[slab][tl] = s2;
    __syncthreads();
    float st = ssum[0][tl] + ssum[1][tl] + ssum[2][tl] + ssum[3][tl];
    float st2 = ssq[0][tl] + ssq[1][tl] + ssq[2][tl] + ssq[3][tl];
    float mu = st * (1.f / HD);
    float var = st2 * (1.f / HD) - mu * mu;
    float rstd = rsqrtf(var + 1e-5f);
    for (int c = slab * 128; c < slab * 128 + 128; ++c) {
        float v = Hbp[(size_t)c * LL + t];
        Hbp[(size_t)c * LL + t] = (v - mu) * rstd * gamma[c] + beta[c];
    }
}

// ---------------- launch ----------------
extern "C" void kernel_launch(void* const* d_in, const int* in_sizes, int n_in,
                              void* d_out, int out_size)
{
    const float* x = (const float*)d_in[0];
    const float* W_enc = (const float*)d_in[1];
    const float* W_dec = (const float*)d_in[2];
    const float* log_dt = (const float*)d_in[3];
    const float* log_A_real = (const float*)d_in[4];
    const float* A_imag = (const float*)d_in[5];
    const float* C_re = (const float*)d_in[6];
    const float* C_im = (const float*)d_in[7];
    const float* Dv = (const float*)d_in[8];
    const float* W_out = (const float*)d_in[9];
    const float* b_out = (const float*)d_in[10];
    const float* ln_g = (const float*)d_in[11];
    const float* ln_b = (const float*)d_in[12];
    float* out = (float*)d_out;

    float *pH, *pY, *pZ, *pwre, *pwim, *pcre, *pcim;
    __nv_bfloat16 *pBth, *pBtl, *pWh, *pWl;
    cudaGetSymbolAddress((void**)&pH, g_H);
    cudaGetSymbolAddress((void**)&pY, g_Y);
    cudaGetSymbolAddress((void**)&pZ, g_Z);
    cudaGetSymbolAddress((void**)&pwre, g_wre);
    cudaGetSymbolAddress((void**)&pwim, g_wim);
    cudaGetSymbolAddress((void**)&pcre, g_cre);
    cudaGetSymbolAddress((void**)&pcim, g_cim);
    cudaGetSymbolAddress((void**)&pBth, g_Bth);
    cudaGetSymbolAddress((void**)&pBtl, g_Btl);
    cudaGetSymbolAddress((void**)&pWh, g_Wh);
    cudaGetSymbolAddress((void**)&pWl, g_Wl);

    cudaFuncSetAttribute(gemm_mma<0>, cudaFuncAttributeMaxDynamicSharedMemorySize, GEMM_SMEM);
    cudaFuncSetAttribute(gemm_mma<1>, cudaFuncAttributeMaxDynamicSharedMemorySize, GEMM_SMEM);

    precompute_kernel<<<(NL * HD * NN + 255) / 256, 256>>>(log_dt, log_A_real,
                                                           A_imag, C_re, C_im);
    split_w_kernel<<<(HD * HD + 255) / 256, 256>>>(W_enc, pWh + W_ENC_OFF,
                                                   pWl + W_ENC_OFF, HD * HD);
    split_w_kernel<<<(NL * 2 * HD * HD + 255) / 256, 256>>>(
        W_out, pWh + W_OUT_OFF, pWl + W_OUT_OFF, NL * 2 * HD * HD);
    split_w_kernel<<<(HD * HD + 255) / 256, 256>>>(W_dec, pWh + W_DEC_OFF,
                                                   pWl + W_DEC_OFF, HD * HD);

    const dim3 tgrid(LL / 32, HD / 32, BQ);

    // encoder: h = relu(W_enc @ quant(x))
    transpose_split_kernel<true><<<tgrid, 256>>>(x, pBth, pBtl);
    gemm_mma<0><<<dim3(NTOT / 128, HD / 128), 256, GEMM_SMEM>>>(
        pWh + W_ENC_OFF, pWl + W_ENC_OFF, pBth, pBtl, pH, nullptr, HD);

    for (int l = 0; l < NL; ++l) {
        int po = l * HD * NN;
        ssm_scan_kernel<<<(BQ * HD * 8) / 256, 256>>>(
            pH, pY, pwre + po, pwim + po, pcre + po, pcim + po, Dv + l * HD);
        transpose_split_kernel<false><<<tgrid, 256>>>(pY, pBth, pBtl);
        gemm_mma<1><<<dim3(NTOT / 128, (2 * HD) / 128), 256, GEMM_SMEM>>>(
            pWh + W_OUT_OFF + (size_t)l * 2 * HD * HD,
            pWl + W_OUT_OFF + (size_t)l * 2 * HD * HD,
            pBth, pBtl, pZ, b_out + l * 2 * HD, 2 * HD);
        glu_res_ln_kernel<<<dim3(LL / 64, BQ), 256>>>(pZ, pH, ln_g + l * HD,
                                                      ln_b + l * HD);
    }

    // decoder: out = relu(W_dec @ h)
    transpose_split_kernel<false><<<tgrid, 256>>>(pH, pBth, pBtl);
    gemm_mma<0><<<dim3(NTOT / 128, HD / 128), 256, GEMM_SMEM>>>(
        pWh + W_DEC_OFF, pWl + W_DEC_OFF, pBth, pBtl, out, nullptr, HD);
}

// round 4
// speedup vs baseline: 1.7764x; 1.1526x over previous
#include <cuda_runtime.h>
#include <cuda_bf16.h>
#include <stdint.h>
#include <math.h>

#define BQ 16
#define HD 512
#define LL 2048
#define NL 4
#define NN 32
#define NTOT (BQ * LL)  // 32768 total columns

// ---------------- scratch (static __device__, no allocs) ----------------
__device__ float g_H[(size_t)BQ * HD * LL];          // residual stream (B,H,L)
__device__ float g_G[(size_t)BQ * HD * LL];          // GLU output (B,H,L)
__device__ __nv_bfloat16 g_Bth[(size_t)NTOT * HD];   // activations (n,k) hi
__device__ __nv_bfloat16 g_Btl[(size_t)NTOT * HD];   // activations (n,k) lo
#define W_ENC_OFF 0
#define W_OUT_OFF (HD * HD)
#define W_DEC_OFF (HD * HD + NL * 2 * HD * HD)
#define W_ELEMS (2 * HD * HD + NL * 2 * HD * HD)
__device__ __nv_bfloat16 g_Wh[W_ELEMS];
__device__ __nv_bfloat16 g_Wl[W_ELEMS];
__device__ float g_wre[NL * HD * NN];
__device__ float g_wim[NL * HD * NN];
__device__ float g_cre[NL * HD * NN];
__device__ float g_cim[NL * HD * NN];

// ---------------- helpers ----------------
__device__ __forceinline__ uint32_t smem_u32(const void* p)
{
    uint32_t a;
    asm("{ .reg .u64 t; cvta.to.shared.u64 t, %1; cvt.u32.u64 %0, t; }"
        : "=r"(a) : "l"(p));
    return a;
}

__device__ __forceinline__ void cp_async16(uint32_t dst, const void* src)
{
    asm volatile("cp.async.cg.shared.global [%0], [%1], 16;" :: "r"(dst), "l"(src));
}
#define CP_COMMIT() asm volatile("cp.async.commit_group;" ::: "memory")
#define CP_WAIT(n)  asm volatile("cp.async.wait_group %0;" :: "n"(n) : "memory")

__device__ __forceinline__ void ldmx4(uint32_t* r, uint32_t addr)
{
    asm volatile("ldmatrix.sync.aligned.m8n8.x4.shared.b16 {%0,%1,%2,%3}, [%4];"
                 : "=r"(r[0]), "=r"(r[1]), "=r"(r[2]), "=r"(r[3]) : "r"(addr));
}

__device__ __forceinline__ void mma16816(float* c, const uint32_t* a,
                                         const uint32_t* b)
{
    asm volatile(
        "mma.sync.aligned.m16n8k16.row.col.f32.bf16.bf16.f32 "
        "{%0,%1,%2,%3}, {%4,%5,%6,%7}, {%8,%9}, {%0,%1,%2,%3};"
        : "+f"(c[0]), "+f"(c[1]), "+f"(c[2]), "+f"(c[3])
        : "r"(a[0]), "r"(a[1]), "r"(a[2]), "r"(a[3]), "r"(b[0]), "r"(b[1]));
}

// ---------------- parameter precompute ----------------
__global__ __launch_bounds__(256)
void precompute_kernel(const float* __restrict__ log_dt,
                       const float* __restrict__ log_A_real,
                       const float* __restrict__ A_imag,
                       const float* __restrict__ C_re,
                       const float* __restrict__ C_im)
{
    int idx = blockIdx.x * 256 + threadIdx.x;
    if (idx >= NL * HD * NN) return;
    int h = (idx >> 5) & (HD - 1);
    int l = idx >> 14;
    float dt = expf(log_dt[l * HD + h]);
    float a = -expf(log_A_real[idx]);
    float b = A_imag[idx];
    float xr = dt * a, xi = dt * b;
    float er = expf(xr);
    float c = cosf(xi), s = sinf(xi);
    g_wre[idx] = er * c;
    g_wim[idx] = er * s;
    float sh = sinf(0.5f * xi);
    float Ere = expm1f(xr) * c - 2.f * sh * sh;
    float Eim = er * s;
    float den = a * a + b * b;
    float Fre = (Ere * a + Eim * b) / den;
    float Fim = (Eim * a - Ere * b) / den;
    float cr = C_re[idx], ci = C_im[idx];
    g_cre[idx] = cr * Fre - ci * Fim;
    g_cim[idx] = cr * Fim + ci * Fre;
}

// ---------------- weight split fp32 -> bf16 hi/lo ----------------
__global__ __launch_bounds__(256)
void split_w_kernel(const float* __restrict__ src, __nv_bfloat16* __restrict__ hi,
                    __nv_bfloat16* __restrict__ lo, int n)
{
    int i = blockIdx.x * 256 + threadIdx.x;
    if (i >= n) return;
    float v = src[i];
    __nv_bfloat16 h = __float2bfloat16(v);
    hi[i] = h;
    lo[i] = __float2bfloat16(v - __bfloat162float(h));
}

// ---------------- activation transpose + split: (B,C,L) -> [(b*L+t)*C + c] ----
template <bool QUANT>
__global__ __launch_bounds__(256)
void transpose_split_kernel(const float* __restrict__ src,
                            __nv_bfloat16* __restrict__ dhi,
                            __nv_bfloat16* __restrict__ dlo)
{
    __shared__ float tile[32][33];
    const int b = blockIdx.z;
    const int c0 = blockIdx.y * 32;
    const int t0 = blockIdx.x * 32;
    const int tx = threadIdx.x & 31, ty = threadIdx.x >> 5;
#pragma unroll
    for (int i = 0; i < 32; i += 8) {
        float v = src[((size_t)b * HD + c0 + ty + i) * LL + t0 + tx];
        if (QUANT) v = rintf(v * 64.f) * 0.015625f;
        tile[ty + i][tx] = v;
    }
    __syncthreads();
#pragma unroll
    for (int i = 0; i < 32; i += 8) {
        int t = t0 + ty + i;
        int c = c0 + tx;
        float v = tile[tx][ty + i];
        __nv_bfloat16 h = __float2bfloat16(v);
        size_t o = ((size_t)b * LL + t) * HD + c;
        dhi[o] = h;
        dlo[o] = __float2bfloat16(v - __bfloat162float(h));
    }
}

// ---------------- HMMA GEMM (3x bf16 split, fp32 acc) ----------------
// CTA tile 128(Mrows) x 128(N), K-chunk 64, double buffered cp.async.
// 8 warps as 4(M)x2(N): each warp 32x64.
// EPI 0: relu -> out (M rows plain)
// EPI 2: fused GLU: A rows interleave z1/z2 16-row blocks; writes
//        g = (z1+b1)*sigmoid(z2+b2), 64 out rows per CTA.
#define KC 64
#define TILE_BYTES 16384            // 128 * 64 * 2B
#define STAGE_BYTES (4 * TILE_BYTES)
#define GEMM_SMEM (2 * STAGE_BYTES) // 131072

template <int EPI>
__global__ __launch_bounds__(256, 1)
void gemm_mma(const __nv_bfloat16* __restrict__ Wh, const __nv_bfloat16* __restrict__ Wl,
              const __nv_bfloat16* __restrict__ Xh, const __nv_bfloat16* __restrict__ Xl,
              float* __restrict__ out, const float* __restrict__ bias, int M)
{
    extern __shared__ char smem[];
    const uint32_t sb = smem_u32(smem);
    const int tid = threadIdx.x;
    const int wid = tid >> 5, lane = tid & 31;
    const int wm = wid >> 1, wn = wid & 1;
    const int n0 = blockIdx.x * 128;
    const int m0 = blockIdx.y * ((EPI == 2) ? 64 : 128);
    const int lr = lane & 7, lg = lane >> 3;

    float acc[2][8][4];
#pragma unroll
    for (int i = 0; i < 2; ++i)
#pragma unroll
        for (int j = 0; j < 8; ++j)
#pragma unroll
            for (int q = 0; q < 4; ++q) acc[i][j][q] = 0.f;

    // cp.async one K-chunk (64 cols) of all 4 tiles into stage st
    auto load_chunk = [&](int kc, int st) {
        const uint32_t base = sb + st * STAGE_BYTES;
        const size_t gk = (size_t)kc * KC;
#pragma unroll
        for (int i = 0; i < 4; ++i) {
            int lin = i * 256 + tid;
            int row = lin >> 3, seg = lin & 7;
            uint32_t soff = row * 128 + (((seg ^ (row & 7))) << 4);
            int wrow;
            if (EPI == 2)
                wrow = ((row >> 4) & 1) * HD + m0 + (row >> 5) * 16 + (row & 15);
            else
                wrow = m0 + row;
            const size_t wgo = (size_t)wrow * HD + gk + seg * 8;
            const size_t xgo = (size_t)(n0 + row) * HD + gk + seg * 8;
            cp_async16(base + soff, Wh + wgo);
            cp_async16(base + TILE_BYTES + soff, Wl + wgo);
            cp_async16(base + 2 * TILE_BYTES + soff, Xh + xgo);
            cp_async16(base + 3 * TILE_BYTES + soff, Xl + xgo);
        }
        CP_COMMIT();
    };

    load_chunk(0, 0);

    const int NCH = HD / KC;  // 8
    for (int c = 0; c < NCH; ++c) {
        if (c + 1 < NCH) {
            load_chunk(c + 1, (c + 1) & 1);
            CP_WAIT(1);
        } else {
            CP_WAIT(0);
        }
        __syncthreads();

        const uint32_t stg = sb + (c & 1) * STAGE_BYTES;
#pragma unroll
        for (int ks = 0; ks < 4; ++ks) {
            uint32_t a[2][2][4];   // [half][mi][reg]
            uint32_t b[2][4][4];   // [half][n16 group][reg]
#pragma unroll
            for (int mi = 0; mi < 2; ++mi) {
                int arow = wm * 32 + mi * 16 + lr + (lg & 1) * 8;
                int aseg = ks * 2 + (lg >> 1);
                uint32_t off = arow * 128 + ((aseg ^ (arow & 7)) << 4);
                ldmx4(a[0][mi], stg + off);
                ldmx4(a[1][mi], stg + TILE_BYTES + off);
            }
#pragma unroll
            for (int g = 0; g < 4; ++g) {
                int brow = wn * 64 + g * 16 + lr + (lg >> 1) * 8;
                int bseg = ks * 2 + (lg & 1);
                uint32_t off = brow * 128 + ((bseg ^ (brow & 7)) << 4);
                ldmx4(b[0][g], stg + 2 * TILE_BYTES + off);
                ldmx4(b[1][g], stg + 3 * TILE_BYTES + off);
            }
#pragma unroll
            for (int mi = 0; mi < 2; ++mi)
#pragma unroll
                for (int j = 0; j < 8; ++j) {
                    const int g = j >> 1, p = (j & 1) * 2;
                    uint32_t bh[2] = {b[0][g][p], b[0][g][p + 1]};
                    uint32_t bl[2] = {b[1][g][p], b[1][g][p + 1]};
                    mma16816(acc[mi][j], a[0][mi], bh);  // ah*bh
                    mma16816(acc[mi][j], a[0][mi], bl);  // ah*bl
                    mma16816(acc[mi][j], a[1][mi], bh);  // al*bh
                }
        }
        __syncthreads();
    }

    // ---------------- epilogue ----------------
    if (EPI == 2) {
        // acc[0] = z1 rows m, acc[1] = z2 rows m (same m)
        const int m = m0 + wm * 16 + (lane >> 2);
        const float b10 = bias[m],      b18 = bias[m + 8];
        const float b20 = bias[HD + m], b28 = bias[HD + m + 8];
#pragma unroll
        for (int j = 0; j < 8; ++j) {
            const int n = n0 + wn * 64 + j * 8 + (lane & 3) * 2;
            const int bb = n >> 11;
            const int t = n & (LL - 1);
            float z10 = acc[0][j][0] + b10, z11 = acc[0][j][1] + b10;
            float z12 = acc[0][j][2] + b18, z13 = acc[0][j][3] + b18;
            float z20 = acc[1][j][0] + b20, z21 = acc[1][j][1] + b20;
            float z22 = acc[1][j][2] + b28, z23 = acc[1][j][3] + b28;
            float2 v0, v1;
            v0.x = z10 / (1.f + expf(-z20));
            v0.y = z11 / (1.f + expf(-z21));
            v1.x = z12 / (1.f + expf(-z22));
            v1.y = z13 / (1.f + expf(-z23));
            *reinterpret_cast<float2*>(out + ((size_t)bb * HD + m) * LL + t) = v0;
            *reinterpret_cast<float2*>(out + ((size_t)bb * HD + m + 8) * LL + t) = v1;
        }
    } else {
#pragma unroll
        for (int mi = 0; mi < 2; ++mi) {
            const int mrow0 = m0 + wm * 32 + mi * 16 + (lane >> 2);
#pragma unroll
            for (int j = 0; j < 8; ++j) {
                const int n = n0 + wn * 64 + j * 8 + (lane & 3) * 2;
                const int bb = n >> 11;
                const int t = n & (LL - 1);
                float2 v0, v1;
                v0.x = fmaxf(acc[mi][j][0], 0.f);
                v0.y = fmaxf(acc[mi][j][1], 0.f);
                v1.x = fmaxf(acc[mi][j][2], 0.f);
                v1.y = fmaxf(acc[mi][j][3], 0.f);
                *reinterpret_cast<float2*>(out + ((size_t)bb * M + mrow0) * LL + t) = v0;
                *reinterpret_cast<float2*>(out + ((size_t)bb * M + mrow0 + 8) * LL + t) = v1;
            }
        }
    }
}

// ---------------- SSM scan fused: reads H, writes gelu(y) as bf16 hi/lo ----
// transposed [(b*L+t)*HD + h] for the following GEMM.
__global__ __launch_bounds__(256)
void ssm_scan_fused(const float* __restrict__ hbuf,
                    __nv_bfloat16* __restrict__ dhi,
                    __nv_bfloat16* __restrict__ dlo,
                    const float* __restrict__ wre, const float* __restrict__ wim,
                    const float* __restrict__ ccre, const float* __restrict__ ccim,
                    const float* __restrict__ Dv)
{
    __shared__ float tile[32][33];
    const int tid = threadIdx.x;
    const int q = tid & 7;
    const int g = tid >> 3;                 // 0..31
    const int grp0 = blockIdx.x * 32;       // aligned to 32, within one b
    const int grp = grp0 + g;
    const int b = grp >> 9;
    const int hh = grp & (HD - 1);
    const int h0 = grp0 & (HD - 1);
    const float* hrow = hbuf + (size_t)grp * LL;

    const int pbase = hh * NN + q * 4;
    float4 w_r = *reinterpret_cast<const float4*>(&wre[pbase]);
    float4 w_i = *reinterpret_cast<const float4*>(&wim[pbase]);
    float4 c_r = *reinterpret_cast<const float4*>(&ccre[pbase]);
    float4 c_i = *reinterpret_cast<const float4*>(&ccim[pbase]);
    float wr[4] = {w_r.x, w_r.y, w_r.z, w_r.w};
    float wi[4] = {w_i.x, w_i.y, w_i.z, w_i.w};
    float cr[4] = {c_r.x, c_r.y, c_r.z, c_r.w};
    float ci[4] = {c_i.x, c_i.y, c_i.z, c_i.w};
    const float Dh = Dv[hh];

    float sr[4] = {0.f, 0.f, 0.f, 0.f};
    float si[4] = {0.f, 0.f, 0.f, 0.f};

    const int tt = tid >> 3, seg = tid & 7;

    for (int t0 = 0; t0 < LL; t0 += 32) {
#pragma unroll
        for (int sub = 0; sub < 4; ++sub) {
            const int tb = t0 + sub * 8;
            float umine = 0.f, ykeep = 0.f;
#pragma unroll
            for (int j = 0; j < 8; ++j) {
                float u = hrow[tb + j];
#pragma unroll
                for (int k = 0; k < 4; ++k) {
                    float nr = fmaf(wr[k], sr[k], u);
                    nr = fmaf(-wi[k], si[k], nr);
                    float ni = wr[k] * si[k];
                    ni = fmaf(wi[k], sr[k], ni);
                    sr[k] = nr;
                    si[k] = ni;
                }
                float acc = 0.f;
#pragma unroll
                for (int k = 0; k < 4; ++k) {
                    acc = fmaf(cr[k], sr[k], acc);
                    acc = fmaf(-ci[k], si[k], acc);
                }
                acc += __shfl_xor_sync(0xffffffffu, acc, 1);
                acc += __shfl_xor_sync(0xffffffffu, acc, 2);
                acc += __shfl_xor_sync(0xffffffffu, acc, 4);
                if (j == q) { umine = u; ykeep = acc; }
            }
            float yv = fmaf(Dh, umine, 2.f * ykeep);
            float gv = 0.5f * yv * (1.f + erff(yv * 0.70710678118654752f));
            tile[sub * 8 + q][g] = gv;
        }
        __syncthreads();
        // drain: row t = t0+tt, 32 channels h0..h0+31, 4 per thread
        {
            const int t = t0 + tt;
            float v0 = tile[tt][seg * 4 + 0];
            float v1 = tile[tt][seg * 4 + 1];
            float v2 = tile[tt][seg * 4 + 2];
            float v3 = tile[tt][seg * 4 + 3];
            __nv_bfloat16 hi4[4], lo4[4];
            hi4[0] = __float2bfloat16(v0);
            hi4[1] = __float2bfloat16(v1);
            hi4[2] = __float2bfloat16(v2);
            hi4[3] = __float2bfloat16(v3);
            lo4[0] = __float2bfloat16(v0 - __bfloat162float(hi4[0]));
            lo4[1] = __float2bfloat16(v1 - __bfloat162float(hi4[1]));
            lo4[2] = __float2bfloat16(v2 - __bfloat162float(hi4[2]));
            lo4[3] = __float2bfloat16(v3 - __bfloat162float(hi4[3]));
            const size_t o = ((size_t)b * LL + t) * HD + h0 + seg * 4;
            *reinterpret_cast<uint2*>(dhi + o) = *reinterpret_cast<uint2*>(hi4);
            *reinterpret_cast<uint2*>(dlo + o) = *reinterpret_cast<uint2*>(lo4);
        }
        __syncthreads();
    }
}

// ---------------- residual + channel LayerNorm ----------------
// H := LN(G + H)
__global__ __launch_bounds__(256)
void res_ln_kernel(const float* __restrict__ G, float* __restrict__ Hb_,
                   const float* __restrict__ gamma, const float* __restrict__ beta)
{
    __shared__ float ssum[4][64];
    __shared__ float ssq[4][64];
    const int b = blockIdx.y;
    const int tl = threadIdx.x & 63;
    const int slab = threadIdx.x >> 6;
    const size_t t = (size_t)blockIdx.x * 64 + tl;
    const float* Gb = G + (size_t)b * HD * LL;
    float* Hbp = Hb_ + (size_t)b * HD * LL;

    float s = 0.f, s2 = 0.f;
    for (int c = slab * 128; c < slab * 128 + 128; ++c) {
        float v = Gb[(size_t)c * LL + t] + Hbp[(size_t)c * LL + t];
        Hbp[(size_t)c * LL + t] = v;
        s += v;
        s2 = fmaf(v, v, s2);
    }
    ssum[slab][tl] = s;
    ssq[slab][tl] = s2;
    __syncthreads();
    float st = ssum[0][tl] + ssum[1][tl] + ssum[2][tl] + ssum[3][tl];
    float st2 = ssq[0][tl] + ssq[1][tl] + ssq[2][tl] + ssq[3][tl];
    float mu = st * (1.f / HD);
    float var = st2 * (1.f / HD) - mu * mu;
    float rstd = rsqrtf(var + 1e-5f);
    for (int c = slab * 128; c < slab * 128 + 128; ++c) {
        float v = Hbp[(size_t)c * LL + t];
        Hbp[(size_t)c * LL + t] = (v - mu) * rstd * gamma[c] + beta[c];
    }
}

// ---------------- launch ----------------
extern "C" void kernel_launch(void* const* d_in, const int* in_sizes, int n_in,
                              void* d_out, int out_size)
{
    const float* x = (const float*)d_in[0];
    const float* W_enc = (const float*)d_in[1];
    const float* W_dec = (const float*)d_in[2];
    const float* log_dt = (const float*)d_in[3];
    const float* log_A_real = (const float*)d_in[4];
    const float* A_imag = (const float*)d_in[5];
    const float* C_re = (const float*)d_in[6];
    const float* C_im = (const float*)d_in[7];
    const float* Dv = (const float*)d_in[8];
    const float* W_out = (const float*)d_in[9];
    const float* b_out = (const float*)d_in[10];
    const float* ln_g = (const float*)d_in[11];
    const float* ln_b = (const float*)d_in[12];
    float* out = (float*)d_out;

    float *pH, *pG, *pwre, *pwim, *pcre, *pcim;
    __nv_bfloat16 *pBth, *pBtl, *pWh, *pWl;
    cudaGetSymbolAddress((void**)&pH, g_H);
    cudaGetSymbolAddress((void**)&pG, g_G);
    cudaGetSymbolAddress((void**)&pwre, g_wre);
    cudaGetSymbolAddress((void**)&pwim, g_wim);
    cudaGetSymbolAddress((void**)&pcre, g_cre);
    cudaGetSymbolAddress((void**)&pcim, g_cim);
    cudaGetSymbolAddress((void**)&pBth, g_Bth);
    cudaGetSymbolAddress((void**)&pBtl, g_Btl);
    cudaGetSymbolAddress((void**)&pWh, g_Wh);
    cudaGetSymbolAddress((void**)&pWl, g_Wl);

    cudaFuncSetAttribute(gemm_mma<0>, cudaFuncAttributeMaxDynamicSharedMemorySize, GEMM_SMEM);
    cudaFuncSetAttribute(gemm_mma<2>, cudaFuncAttributeMaxDynamicSharedMemorySize, GEMM_SMEM);

    precompute_kernel<<<(NL * HD * NN + 255) / 256, 256>>>(log_dt, log_A_real,
                                                           A_imag, C_re, C_im);
    split_w_kernel<<<(HD * HD + 255) / 256, 256>>>(W_enc, pWh + W_ENC_OFF,
                                                   pWl + W_ENC_OFF, HD * HD);
    split_w_kernel<<<(NL * 2 * HD * HD + 255) / 256, 256>>>(
        W_out, pWh + W_OUT_OFF, pWl + W_OUT_OFF, NL * 2 * HD * HD);
    split_w_kernel<<<(HD * HD + 255) / 256, 256>>>(W_dec, pWh + W_DEC_OFF,
                                                   pWl + W_DEC_OFF, HD * HD);

    const dim3 tgrid(LL / 32, HD / 32, BQ);

    // encoder: h = relu(W_enc @ quant(x))
    transpose_split_kernel<true><<<tgrid, 256>>>(x, pBth, pBtl);
    gemm_mma<0><<<dim3(NTOT / 128, HD / 128), 256, GEMM_SMEM>>>(
        pWh + W_ENC_OFF, pWl + W_ENC_OFF, pBth, pBtl, pH, nullptr, HD);

    for (int l = 0; l < NL; ++l) {
        int po = l * HD * NN;
        // scan + gelu -> transposed bf16 hi/lo directly
        ssm_scan_fused<<<(BQ * HD) / 32, 256>>>(
            pH, pBth, pBtl, pwre + po, pwim + po, pcre + po, pcim + po,
            Dv + l * HD);
        // fused GLU GEMM: writes g = (z1+b1)*sigmoid(z2+b2)
        gemm_mma<2><<<dim3(NTOT / 128, HD / 64), 256, GEMM_SMEM>>>(
            pWh + W_OUT_OFF + (size_t)l * 2 * HD * HD,
            pWl + W_OUT_OFF + (size_t)l * 2 * HD * HD,
            pBth, pBtl, pG, b_out + l * 2 * HD, HD);
        // residual + LN
        res_ln_kernel<<<dim3(LL / 64, BQ), 256>>>(pG, pH, ln_g + l * HD,
                                                  ln_b + l * HD);
    }

    // decoder: out = relu(W_dec @ h)
    transpose_split_kernel<false><<<tgrid, 256>>>(pH, pBth, pBtl);
    gemm_mma<0><<<dim3(NTOT / 128, HD / 128), 256, GEMM_SMEM>>>(
        pWh + W_DEC_OFF, pWl + W_DEC_OFF, pBth, pBtl, out, nullptr, HD);
}